// round 5
// baseline (speedup 1.0000x reference)
#include <cuda_runtime.h>

// RWKV TimeMix: mix -> 3x GEMM (k,v,r) -> WKV scan * sigmoid(r) -> output GEMM
// Shapes: B=32, T=256, C=1024. All fp32.
// GEMM pattern: D[m,d] = sum_c A[m,c] * W[d,c]  (both K-major, row-major storage)

#define BB 32
#define TT 256
#define CC 1024
#define MMROWS (BB * TT)          // 8192
#define SZ (BB * TT * CC)         // 8,388,608 elements

// Scratch (device globals: allocation-free per harness rules)
__device__ float g_xk[SZ];
__device__ float g_xv[SZ];
__device__ float g_xr[SZ];
__device__ float g_k[SZ];
__device__ float g_v[SZ];
__device__ float g_r[SZ];
__device__ float g_y[SZ];

// ---------------------------------------------------------------------------
// packed f32x2 helpers (Blackwell dual-rate fp32 path)
// ---------------------------------------------------------------------------
__device__ __forceinline__ unsigned long long pk2(float lo, float hi) {
    unsigned long long r;
    asm("mov.b64 %0, {%1, %2};" : "=l"(r) : "f"(lo), "f"(hi));
    return r;
}
__device__ __forceinline__ void fma2(unsigned long long& d,
                                     unsigned long long a,
                                     unsigned long long b) {
    asm("fma.rn.f32x2 %0, %1, %2, %0;" : "+l"(d) : "l"(a), "l"(b));
}

// ---------------------------------------------------------------------------
// SGEMM body: 128x128 block tile, BK=16, 256 threads, 8x8 per-thread tile,
// accumulators packed as f32x2 pairs along N.
// ---------------------------------------------------------------------------
#define BM 128
#define BN 128
#define BKK 16

__device__ __forceinline__ void gemm_body(const float* __restrict__ A,
                                          const float* __restrict__ W,
                                          float* __restrict__ D,
                                          int M, int N, int K) {
    __shared__ float As[BKK][BM + 4];   // +4 pad keeps float4 alignment, tames conflicts
    __shared__ float Bs[BKK][BN + 4];

    const int tid = threadIdx.x;
    const int tx = tid & 15;        // n-dir thread coord (0..15)
    const int ty = tid >> 4;        // m-dir thread coord (0..15)
    const int ldr = tid >> 2;       // load row (0..63)
    const int ldc = tid & 3;        // load float4 column (0..3)

    const float* Ab = A + (size_t)blockIdx.y * BM * K;
    const float* Wb = W + (size_t)blockIdx.x * BN * K;

    unsigned long long acc[8][4];
#pragma unroll
    for (int i = 0; i < 8; i++)
#pragma unroll
        for (int j = 0; j < 4; j++) acc[i][j] = 0ull;

    for (int k0 = 0; k0 < K; k0 += BKK) {
        // global loads (issued before sync so latency overlaps previous compute)
        float4 a0 = *(const float4*)(Ab + (size_t)ldr * K + k0 + ldc * 4);
        float4 a1 = *(const float4*)(Ab + (size_t)(ldr + 64) * K + k0 + ldc * 4);
        float4 b0 = *(const float4*)(Wb + (size_t)ldr * K + k0 + ldc * 4);
        float4 b1 = *(const float4*)(Wb + (size_t)(ldr + 64) * K + k0 + ldc * 4);

        __syncthreads();   // previous tile's compute done before overwrite
#pragma unroll
        for (int j = 0; j < 4; j++) {
            As[ldc * 4 + j][ldr]      = ((const float*)&a0)[j];
            As[ldc * 4 + j][ldr + 64] = ((const float*)&a1)[j];
            Bs[ldc * 4 + j][ldr]      = ((const float*)&b0)[j];
            Bs[ldc * 4 + j][ldr + 64] = ((const float*)&b1)[j];
        }
        __syncthreads();

#pragma unroll
        for (int k = 0; k < BKK; k++) {
            float4 aA = *(const float4*)&As[k][ty * 8];
            float4 aB = *(const float4*)&As[k][ty * 8 + 4];
            float4 bA = *(const float4*)&Bs[k][tx * 8];
            float4 bB = *(const float4*)&Bs[k][tx * 8 + 4];
            unsigned long long p0 = pk2(bA.x, bA.y);
            unsigned long long p1 = pk2(bA.z, bA.w);
            unsigned long long p2 = pk2(bB.x, bB.y);
            unsigned long long p3 = pk2(bB.z, bB.w);
            float av[8] = {aA.x, aA.y, aA.z, aA.w, aB.x, aB.y, aB.z, aB.w};
#pragma unroll
            for (int i = 0; i < 8; i++) {
                unsigned long long ad = pk2(av[i], av[i]);
                fma2(acc[i][0], ad, p0);
                fma2(acc[i][1], ad, p1);
                fma2(acc[i][2], ad, p2);
                fma2(acc[i][3], ad, p3);
            }
        }
    }

    float* Dp = D + (size_t)(blockIdx.y * BM + ty * 8) * N + blockIdx.x * BN + tx * 8;
#pragma unroll
    for (int i = 0; i < 8; i++) {
#pragma unroll
        for (int j = 0; j < 4; j++) {
            // packed pair (n, n+1), 8B-aligned store
            *reinterpret_cast<unsigned long long*>(Dp + (size_t)i * N + 2 * j) = acc[i][j];
        }
    }
}

// z = 0/1/2 selects (xk,Wk->k), (xv,Wv->v), (xr,Wr->r)
__global__ __launch_bounds__(256, 2)
void gemm3_kernel(const float* __restrict__ Wk,
                  const float* __restrict__ Wv,
                  const float* __restrict__ Wr) {
    const float* A;
    const float* W;
    float* D;
    if (blockIdx.z == 0)      { A = g_xk; W = Wk; D = g_k; }
    else if (blockIdx.z == 1) { A = g_xv; W = Wv; D = g_v; }
    else                      { A = g_xr; W = Wr; D = g_r; }
    gemm_body(A, W, D, MMROWS, CC, CC);
}

__global__ __launch_bounds__(256, 2)
void gemm_out_kernel(const float* __restrict__ Wo, float* __restrict__ out) {
    gemm_body(g_y, Wo, out, MMROWS, CC, CC);
}

// ---------------------------------------------------------------------------
// Mix kernel: xk/xv/xr = xx + m*(x - xx), xx = time-shifted x (xx[t]=x[t-1], 0 at t=0)
// ---------------------------------------------------------------------------
__global__ void mix_kernel(const float* __restrict__ x,
                           const float* __restrict__ tmk,
                           const float* __restrict__ tmv,
                           const float* __restrict__ tmr) {
    const int n4 = SZ / 4;
    int i = blockIdx.x * blockDim.x + threadIdx.x;
    if (i >= n4) return;
    const int cpt = CC / 4;                 // float4s per (b,t) row
    int c4 = i & (cpt - 1);
    int t  = (i / cpt) & (TT - 1);

    const float4* x4 = (const float4*)x;
    float4 xc = x4[i];
    float4 xp = make_float4(0.f, 0.f, 0.f, 0.f);
    if (t != 0) xp = x4[i - cpt];

    float4 mk = ((const float4*)tmk)[c4];
    float4 mv = ((const float4*)tmv)[c4];
    float4 mr = ((const float4*)tmr)[c4];

    float4 ok, ov, orr;
    ok.x  = xp.x + mk.x * (xc.x - xp.x);
    ok.y  = xp.y + mk.y * (xc.y - xp.y);
    ok.z  = xp.z + mk.z * (xc.z - xp.z);
    ok.w  = xp.w + mk.w * (xc.w - xp.w);
    ov.x  = xp.x + mv.x * (xc.x - xp.x);
    ov.y  = xp.y + mv.y * (xc.y - xp.y);
    ov.z  = xp.z + mv.z * (xc.z - xp.z);
    ov.w  = xp.w + mv.w * (xc.w - xp.w);
    orr.x = xp.x + mr.x * (xc.x - xp.x);
    orr.y = xp.y + mr.y * (xc.y - xp.y);
    orr.z = xp.z + mr.z * (xc.z - xp.z);
    orr.w = xp.w + mr.w * (xc.w - xp.w);

    ((float4*)g_xk)[i] = ok;
    ((float4*)g_xv)[i] = ov;
    ((float4*)g_xr)[i] = orr;
}

// ---------------------------------------------------------------------------
// WKV scan (numerically-stabilized) fused with sigmoid(r) gate.
// One thread per (b,c) channel, coalesced along c, sequential over T.
// ---------------------------------------------------------------------------
__global__ void wkv_kernel(const float* __restrict__ time_decay,
                           const float* __restrict__ time_first) {
    int gid = blockIdx.x * blockDim.x + threadIdx.x;
    if (gid >= BB * CC) return;
    int b = gid / CC;
    int c = gid & (CC - 1);

    float w = -__expf(time_decay[c]);   // negative log-decay
    float u = time_first[c];

    float p = 0.f, q = 0.f, o = -1e38f;
    size_t off = (size_t)b * TT * CC + c;

#pragma unroll 2
    for (int t = 0; t < TT; t++, off += CC) {
        float kt = g_k[off];
        float vt = g_v[off];
        float rt = g_r[off];

        float uk = u + kt;
        float no = fmaxf(o, uk);
        float eA = __expf(o - no);
        float eB = __expf(uk - no);
        float y  = __fdividef(eA * p + eB * vt, eA * q + eB);

        float sr = __fdividef(1.f, 1.f + __expf(-rt));
        g_y[off] = sr * y;

        float wo  = w + o;
        float no2 = fmaxf(wo, kt);
        float A2  = __expf(wo - no2);
        float B2  = __expf(kt - no2);
        p = A2 * p + B2 * vt;
        q = A2 * q + B2;
        o = no2;
    }
}

// ---------------------------------------------------------------------------
extern "C" void kernel_launch(void* const* d_in, const int* in_sizes, int n_in,
                              void* d_out, int out_size) {
    const float* x   = (const float*)d_in[0];
    const float* td  = (const float*)d_in[1];
    const float* tf  = (const float*)d_in[2];
    const float* tmk = (const float*)d_in[3];
    const float* tmv = (const float*)d_in[4];
    const float* tmr = (const float*)d_in[5];
    const float* Wk  = (const float*)d_in[6];
    const float* Wv  = (const float*)d_in[7];
    const float* Wr  = (const float*)d_in[8];
    const float* Wo  = (const float*)d_in[9];
    float* out = (float*)d_out;

    const int n4 = SZ / 4;
    mix_kernel<<<(n4 + 255) / 256, 256>>>(x, tmk, tmv, tmr);

    dim3 g3(CC / BN, MMROWS / BM, 3);
    gemm3_kernel<<<g3, 256>>>(Wk, Wv, Wr);

    wkv_kernel<<<(BB * CC + 127) / 128, 128>>>(td, tf);

    dim3 go(CC / BN, MMROWS / BM, 1);
    gemm_out_kernel<<<go, 256>>>(Wo, out);
}

// round 8
// speedup vs baseline: 1.8610x; 1.8610x over previous
#include <cuda_runtime.h>
#include <cuda_bf16.h>
#include <cstdint>

// RWKV TimeMix on GB300 (compute_103-safe tensor path):
//   mix(bf16 split) -> 3x HMMA GEMM (k,v,r) -> WKV*sigmoid(r) (bf16 split y)
//   -> HMMA output GEMM.
// GEMM: D[m,d] = sum_c A[m,c]*W[d,c]; fp32 accuracy via bf16 3-term split:
//   D = Ah*Wh + Ah*Wl + Al*Wh     (lo*lo dropped, ~2^-18 relative)
// mma.sync.m16n8k16.row.col: A row-major (m,k), B col-major (k,n) == W[d,c]
// with c contiguous -> both operands used as-stored.

#define BB 32
#define TT 256
#define CC 1024
#define MROWS (BB * TT)                 // 8192
#define SZ (BB * TT * CC)               // 8,388,608
#define WSZ (CC * CC)                   // 1,048,576

// ------------------------- device scratch (no allocs) -----------------------
__device__ __nv_bfloat16 g_a_hi[3 * SZ];   // xk,xv,xr hi
__device__ __nv_bfloat16 g_a_lo[3 * SZ];   // xk,xv,xr lo
__device__ __nv_bfloat16 g_w_hi[4 * WSZ];  // Wk,Wv,Wr,Wo hi
__device__ __nv_bfloat16 g_w_lo[4 * WSZ];  // Wk,Wv,Wr,Wo lo
__device__ float         g_kvr[3 * SZ];    // k,v,r (fp32)
__device__ __nv_bfloat16 g_y_hi[SZ];
__device__ __nv_bfloat16 g_y_lo[SZ];

// ------------------------------ PTX helpers --------------------------------
__device__ __forceinline__ uint32_t smem_u32(const void* p) {
    uint32_t a;
    asm("{ .reg .u64 t; cvta.to.shared.u64 t, %1; cvt.u32.u64 %0, t; }"
        : "=r"(a) : "l"(p));
    return a;
}
__device__ __forceinline__ void cp16(uint32_t dst, const void* src) {
    asm volatile("cp.async.cg.shared.global [%0], [%1], 16;" :: "r"(dst), "l"(src));
}
#define CP_COMMIT() asm volatile("cp.async.commit_group;" ::: "memory")
#define CP_WAIT(n)  asm volatile("cp.async.wait_group %0;" :: "n"(n) : "memory")

__device__ __forceinline__ void ldsm4(uint32_t* r, uint32_t a) {
    asm volatile("ldmatrix.sync.aligned.m8n8.x4.shared.b16 {%0,%1,%2,%3}, [%4];"
        : "=r"(r[0]), "=r"(r[1]), "=r"(r[2]), "=r"(r[3]) : "r"(a));
}
__device__ __forceinline__ void mma16816(float* c, const uint32_t* a, const uint32_t* b) {
    asm volatile("mma.sync.aligned.m16n8k16.row.col.f32.bf16.bf16.f32 "
        "{%0,%1,%2,%3}, {%4,%5,%6,%7}, {%8,%9}, {%0,%1,%2,%3};"
        : "+f"(c[0]), "+f"(c[1]), "+f"(c[2]), "+f"(c[3])
        : "r"(a[0]), "r"(a[1]), "r"(a[2]), "r"(a[3]), "r"(b[0]), "r"(b[1]));
}

// Split two floats -> bf16 hi pair + lo pair (memory order a then b).
__device__ __forceinline__ void split2(float a, float b, uint32_t& h2, uint32_t& l2) {
    asm("cvt.rn.bf16x2.f32 %0, %1, %2;" : "=r"(h2) : "f"(b), "f"(a));
    float ha = __uint_as_float(h2 << 16);
    float hb = __uint_as_float(h2 & 0xFFFF0000u);
    asm("cvt.rn.bf16x2.f32 %0, %1, %2;" : "=r"(l2) : "f"(b - hb), "f"(a - ha));
}

// ------------------------------ GEMM config --------------------------------
#define CTA_M 256
#define CTA_N 128
#define KCHUNK 32
#define NCHUNK (CC / KCHUNK)       // 32
#define LDS_ROW 40                  // bf16/row: 32 data + 8 pad
#define ROWB (LDS_ROW * 2)          // 80 bytes; conflict-free ldmatrix stride
#define SM_AH 0
#define SM_AL 20480                 // 256*80
#define SM_WH 40960
#define SM_WL 51200                 // +128*80
#define STAGE 61440
#define SMEM_BYTES (2 * STAGE)      // 122880

__device__ __forceinline__ void gemm_mma_body(
    const __nv_bfloat16* __restrict__ Ahi, const __nv_bfloat16* __restrict__ Alo,
    const __nv_bfloat16* __restrict__ Whi, const __nv_bfloat16* __restrict__ Wlo,
    float* __restrict__ D)
{
    extern __shared__ char smem[];
    const uint32_t sb = smem_u32(smem);
    const int tid = threadIdx.x;
    const int wid = tid >> 5;
    const int lane = tid & 31;
    const int wm = wid >> 1;              // 0..3  (64-row band)
    const int wn = wid & 1;               // 0..1  (64-col band)
    const int gm = blockIdx.y * CTA_M;
    const int gn = blockIdx.x * CTA_N;

    float acc[4][8][4];
#pragma unroll
    for (int i = 0; i < 4; i++)
#pragma unroll
        for (int j = 0; j < 8; j++)
#pragma unroll
            for (int q = 0; q < 4; q++) acc[i][j][q] = 0.f;

    // lane-invariant ldmatrix offsets
    const int a_row = wm * 64 + (lane & 7) + ((lane >> 3) & 1) * 8;  // + mi*16
    const int a_kof = (lane >> 4) * 8;                               // + k0
    const int b_row = wn * 64 + lane;                                // + g*32

    // cp.async loader: 3072 x 16B per chunk, 12 per thread
    const __nv_bfloat16* gA[2] = { Ahi + (size_t)gm * CC, Alo + (size_t)gm * CC };
    const __nv_bfloat16* gW[2] = { Whi + (size_t)gn * CC, Wlo + (size_t)gn * CC };

#define LOAD_CHUNK(ck, stg) do {                                              \
    uint32_t s0 = sb + (stg) * STAGE;                                         \
    int kc = (ck) * KCHUNK;                                                   \
    _Pragma("unroll")                                                         \
    for (int i = 0; i < 12; i++) {                                            \
        int idx = tid + i * 256;                                              \
        if (i < 8) {                                                          \
            int ty = idx >> 10, rem = idx & 1023;                             \
            int row = rem >> 2, c = rem & 3;                                  \
            cp16(s0 + ty * 20480 + row * ROWB + c * 16,                       \
                 gA[ty] + (size_t)row * CC + kc + c * 8);                     \
        } else {                                                              \
            int w = idx - 2048;                                               \
            int ty = w >> 9, rem = w & 511;                                   \
            int row = rem >> 2, c = rem & 3;                                  \
            cp16(s0 + 40960 + ty * 10240 + row * ROWB + c * 16,               \
                 gW[ty] + (size_t)row * CC + kc + c * 8);                     \
        }                                                                     \
    }                                                                         \
    CP_COMMIT();                                                              \
} while (0)

    LOAD_CHUNK(0, 0);

    for (int ck = 0; ck < NCHUNK; ck++) {
        const int stg = ck & 1;
        if (ck + 1 < NCHUNK) { LOAD_CHUNK(ck + 1, stg ^ 1); CP_WAIT(1); }
        else                 { CP_WAIT(0); }
        __syncthreads();

        const uint32_t s0 = sb + stg * STAGE;
#pragma unroll
        for (int k0 = 0; k0 < KCHUNK; k0 += 16) {
            uint32_t ah[4][4], al[4][4];
#pragma unroll
            for (int mi = 0; mi < 4; mi++) {
                uint32_t addr = s0 + SM_AH + (uint32_t)((a_row + mi * 16) * ROWB + (k0 + a_kof) * 2);
                ldsm4(ah[mi], addr);
                ldsm4(al[mi], addr + (SM_AL - SM_AH));
            }
#pragma unroll
            for (int g = 0; g < 2; g++) {
                uint32_t t0[4], t1[4], u0[4], u1[4];
                uint32_t base = s0 + SM_WH + (uint32_t)((b_row + g * 32) * ROWB + k0 * 2);
                ldsm4(t0, base);                      // Wh, k-half 0 (subtiles 0..3)
                ldsm4(t1, base + 16);                 // Wh, k-half 1
                ldsm4(u0, base + (SM_WL - SM_WH));    // Wl, k-half 0
                ldsm4(u1, base + (SM_WL - SM_WH) + 16);
#pragma unroll
                for (int s = 0; s < 4; s++) {
                    uint32_t bh[2] = { t0[s], t1[s] };
                    uint32_t bl[2] = { u0[s], u1[s] };
#pragma unroll
                    for (int mi = 0; mi < 4; mi++) {
                        float* a = acc[mi][g * 4 + s];
                        mma16816(a, ah[mi], bh);
                        mma16816(a, ah[mi], bl);
                        mma16816(a, al[mi], bh);
                    }
                }
            }
        }
        __syncthreads();
    }
#undef LOAD_CHUNK

    // epilogue: thread t holds rows {trow, trow+8}, cols {tcol, tcol+1} per mma
    const int trow = lane >> 2;
    const int tcol = (lane & 3) * 2;
#pragma unroll
    for (int mi = 0; mi < 4; mi++) {
#pragma unroll
        for (int ni = 0; ni < 8; ni++) {
            float* dp = D + (size_t)(gm + wm * 64 + mi * 16 + trow) * CC
                          + gn + wn * 64 + ni * 8 + tcol;
            float2 v0 = { acc[mi][ni][0], acc[mi][ni][1] };
            float2 v1 = { acc[mi][ni][2], acc[mi][ni][3] };
            *(float2*)dp = v0;
            *(float2*)(dp + 8 * CC) = v1;
        }
    }
}

__global__ __launch_bounds__(256, 1)
void gemm3_mma() {
    const int z = blockIdx.z;
    gemm_mma_body(g_a_hi + (size_t)z * SZ, g_a_lo + (size_t)z * SZ,
                  g_w_hi + (size_t)z * WSZ, g_w_lo + (size_t)z * WSZ,
                  g_kvr + (size_t)z * SZ);
}

__global__ __launch_bounds__(256, 1)
void gemm_out_mma(float* __restrict__ out) {
    gemm_mma_body(g_y_hi, g_y_lo, g_w_hi + 3 * WSZ, g_w_lo + 3 * WSZ, out);
}

// ------------------------------- mix kernel ---------------------------------
__global__ void mix_kernel(const float* __restrict__ x,
                           const float* __restrict__ tmk,
                           const float* __restrict__ tmv,
                           const float* __restrict__ tmr) {
    const int n4 = SZ / 4;
    int i = blockIdx.x * blockDim.x + threadIdx.x;
    if (i >= n4) return;
    const int cpt = CC / 4;
    int c4 = i & (cpt - 1);
    int t  = (i / cpt) & (TT - 1);

    const float4* x4 = (const float4*)x;
    float4 xc = x4[i];
    float4 xp = make_float4(0.f, 0.f, 0.f, 0.f);
    if (t != 0) xp = x4[i - cpt];

    const float4 ms[3] = { ((const float4*)tmk)[c4],
                           ((const float4*)tmv)[c4],
                           ((const float4*)tmr)[c4] };
#pragma unroll
    for (int z = 0; z < 3; z++) {
        float4 m = ms[z];
        float a = xp.x + m.x * (xc.x - xp.x);
        float b = xp.y + m.y * (xc.y - xp.y);
        float c = xp.z + m.z * (xc.z - xp.z);
        float d = xp.w + m.w * (xc.w - xp.w);
        uint2 h, l;
        split2(a, b, h.x, l.x);
        split2(c, d, h.y, l.y);
        ((uint2*)g_a_hi)[(size_t)z * (SZ / 4) + i] = h;
        ((uint2*)g_a_lo)[(size_t)z * (SZ / 4) + i] = l;
    }
}

// --------------------------- weight split kernel ----------------------------
__global__ void wsplit_kernel(const float* __restrict__ Wk, const float* __restrict__ Wv,
                              const float* __restrict__ Wr, const float* __restrict__ Wo) {
    int i = blockIdx.x * blockDim.x + threadIdx.x;       // one float4 each
    const int per = WSZ / 4;                             // 262144
    if (i >= 4 * per) return;
    int z = i >> 18;
    int loc = i & (per - 1);
    const float* W = (z == 0) ? Wk : (z == 1) ? Wv : (z == 2) ? Wr : Wo;
    float4 v = ((const float4*)W)[loc];
    uint2 h, l;
    split2(v.x, v.y, h.x, l.x);
    split2(v.z, v.w, h.y, l.y);
    ((uint2*)g_w_hi)[(size_t)z * per + loc] = h;
    ((uint2*)g_w_lo)[(size_t)z * per + loc] = l;
}

// ------------------------------- WKV kernel ---------------------------------
__global__ void wkv_kernel(const float* __restrict__ time_decay,
                           const float* __restrict__ time_first) {
    int gid = blockIdx.x * blockDim.x + threadIdx.x;
    if (gid >= BB * CC) return;
    int b = gid / CC;
    int c = gid & (CC - 1);

    const float* kk = g_kvr;
    const float* vv = g_kvr + SZ;
    const float* rr = g_kvr + 2 * (size_t)SZ;

    float w = -__expf(time_decay[c]);
    float u = time_first[c];

    float p = 0.f, q = 0.f, o = -1e38f;
    size_t off = (size_t)b * TT * CC + c;

#pragma unroll 2
    for (int t = 0; t < TT; t++, off += CC) {
        float kt = kk[off];
        float vt = vv[off];
        float rt = rr[off];

        float uk = u + kt;
        float no = fmaxf(o, uk);
        float eA = __expf(o - no);
        float eB = __expf(uk - no);
        float y  = __fdividef(eA * p + eB * vt, eA * q + eB);

        float sr = __fdividef(1.f, 1.f + __expf(-rt));
        float f = sr * y;
        __nv_bfloat16 h = __float2bfloat16(f);
        g_y_hi[off] = h;
        g_y_lo[off] = __float2bfloat16(f - __bfloat162float(h));

        float wo  = w + o;
        float no2 = fmaxf(wo, kt);
        float A2  = __expf(wo - no2);
        float B2  = __expf(kt - no2);
        p = A2 * p + B2 * vt;
        q = A2 * q + B2;
        o = no2;
    }
}

// ---------------------------------------------------------------------------
extern "C" void kernel_launch(void* const* d_in, const int* in_sizes, int n_in,
                              void* d_out, int out_size) {
    const float* x   = (const float*)d_in[0];
    const float* td  = (const float*)d_in[1];
    const float* tf  = (const float*)d_in[2];
    const float* tmk = (const float*)d_in[3];
    const float* tmv = (const float*)d_in[4];
    const float* tmr = (const float*)d_in[5];
    const float* Wk  = (const float*)d_in[6];
    const float* Wv  = (const float*)d_in[7];
    const float* Wr  = (const float*)d_in[8];
    const float* Wo  = (const float*)d_in[9];
    float* out = (float*)d_out;

    static bool attr_set = false;
    if (!attr_set) {
        cudaFuncSetAttribute(gemm3_mma, cudaFuncAttributeMaxDynamicSharedMemorySize, SMEM_BYTES);
        cudaFuncSetAttribute(gemm_out_mma, cudaFuncAttributeMaxDynamicSharedMemorySize, SMEM_BYTES);
        attr_set = true;
    }

    const int n4 = SZ / 4;
    mix_kernel<<<(n4 + 255) / 256, 256>>>(x, tmk, tmv, tmr);
    wsplit_kernel<<<(WSZ + 255) / 256, 256>>>(Wk, Wv, Wr, Wo);

    dim3 g3(CC / CTA_N, MROWS / CTA_M, 3);
    gemm3_mma<<<g3, 256, SMEM_BYTES>>>();

    wkv_kernel<<<(BB * CC + 127) / 128, 128>>>(td, tf);

    dim3 go(CC / CTA_N, MROWS / CTA_M, 1);
    gemm_out_mma<<<go, 256, SMEM_BYTES>>>(out);
}